// round 8
// baseline (speedup 1.0000x reference)
#include <cuda_runtime.h>
#include <cuda_bf16.h>
#include <cuda_fp16.h>
#include <mma.h>
#include <cstdint>

using namespace nvcuda;

// Problem constants (fixed-shape problem, from reference_code)
#define N_NODES 100000
#define D_FEAT  256
#define H1      128
#define H2      64
#define N_EDGES 1600000

#define SCAN_BLK 1024
#define N_SCAN_BLOCKS ((N_NODES + SCAN_BLK - 1) / SCAN_BLK)   // 98

// Scratch buffers (device globals: allocation-free scratch).
__device__ __half g_xw0h[(size_t)N_NODES * H1];  // X @ W0, fp16 (gather operand)
__device__ __half g_hw1h[(size_t)N_NODES * H2];  // relu(h1) @ W1, fp16 (gather operand)
__device__ int    g_is64;                        // edge index dtype flag

// CSR (by dst) built fresh each launch; col+weight packed in one int2
__device__ int   g_cnt [N_NODES];                // histogram, then cursor
__device__ int   g_ptr [N_NODES + 1];            // row pointers
__device__ int   g_bsum[N_SCAN_BLOCKS];
__device__ int2  g_edge[N_EDGES];                // {col, __float_as_int(w)}

// ---------------------------------------------------------------------------
// f32x2 packed math (sm_103a; PTX-only — ptxas never auto-fuses)
// ---------------------------------------------------------------------------
__device__ __forceinline__ unsigned long long pack2(float x, float y) {
    unsigned long long r;
    asm("mov.b64 %0, {%1, %2};" : "=l"(r) : "f"(x), "f"(y));
    return r;
}
__device__ __forceinline__ void unpack2(unsigned long long v, float& x, float& y) {
    asm("mov.b64 {%0, %1}, %2;" : "=f"(x), "=f"(y) : "l"(v));
}
__device__ __forceinline__ void fma2(unsigned long long& d,
                                     unsigned long long a,
                                     unsigned long long b) {
    asm("fma.rn.f32x2 %0, %1, %2, %0;" : "+l"(d) : "l"(a), "l"(b));
}

// ---------------------------------------------------------------------------
// dtype probe (thread 0) + zero histogram (whole grid)
// ---------------------------------------------------------------------------
__global__ void detect_zero_kernel(const void* __restrict__ src) {
    int i = blockIdx.x * blockDim.x + threadIdx.x;
    if (i < N_NODES) g_cnt[i] = 0;
    if (i == 0) {
        const long long* p = (const long long*)src;
        int ok = 1;
        for (int k = 0; k < 64; k++) {
            long long v = p[k];
            if (v < 0 || v >= N_NODES) { ok = 0; break; }
        }
        g_is64 = ok;
    }
}

__device__ __forceinline__ int load_idx(const void* p, int e, int is64) {
    return is64 ? (int)((const long long*)p)[e] : ((const int*)p)[e];
}

// ---------------------------------------------------------------------------
// CSR build: histogram -> scan(2 kernels) -> scatter
// ---------------------------------------------------------------------------
__global__ void hist_kernel(const void* __restrict__ dst, int E) {
    int e = blockIdx.x * blockDim.x + threadIdx.x;
    if (e >= E) return;
    int d = load_idx(dst, e, g_is64);
    if ((unsigned)d < N_NODES) atomicAdd(&g_cnt[d], 1);
}

__global__ void scan1_kernel() {
    __shared__ int s[SCAN_BLK];
    int i = blockIdx.x * SCAN_BLK + threadIdx.x;
    int v = (i < N_NODES) ? g_cnt[i] : 0;
    s[threadIdx.x] = v;
    __syncthreads();
#pragma unroll
    for (int o = 1; o < SCAN_BLK; o <<= 1) {
        int t = (threadIdx.x >= o) ? s[threadIdx.x - o] : 0;
        __syncthreads();
        s[threadIdx.x] += t;
        __syncthreads();
    }
    int inc = s[threadIdx.x];
    if (i < N_NODES) g_ptr[i] = inc - v;
    if (threadIdx.x == SCAN_BLK - 1) g_bsum[blockIdx.x] = inc;
}

// scan3 with scan2 folded in: 2 threads/block compute the (<=2) block-sum
// prefixes this 256-wide block can touch.
__global__ void scan3_kernel(int E) {
    __shared__ int soff[2];
    int base = blockIdx.x * blockDim.x;
    int b0 = base / SCAN_BLK;
    if (threadIdx.x < 2) {
        int b = b0 + threadIdx.x;
        int off = 0;
        for (int j = 0; j < b && j < N_SCAN_BLOCKS; j++) off += g_bsum[j];
        soff[threadIdx.x] = off;
    }
    __syncthreads();
    int i = base + threadIdx.x;
    if (i < N_NODES) {
        int p = g_ptr[i] + soff[i / SCAN_BLK - b0];
        g_ptr[i] = p;
        g_cnt[i] = p;                     // cursor for scatter
    }
    if (i == 0) g_ptr[N_NODES] = E;
}

__global__ void scatter_kernel(const void* __restrict__ src,
                               const void* __restrict__ dst,
                               const float* __restrict__ w, int E) {
    int e = blockIdx.x * blockDim.x + threadIdx.x;
    if (e >= E) return;
    int is64 = g_is64;
    int s = load_idx(src, e, is64);
    int d = load_idx(dst, e, is64);
    if ((unsigned)s >= N_NODES || (unsigned)d >= N_NODES) return;
    int pos = atomicAdd(&g_cnt[d], 1);
    g_edge[pos] = make_int2(s, __float_as_int(w[e]));
}

// ---------------------------------------------------------------------------
// GEMM1: tensor-core (wmma fp16 in / fp32 accum), output fp16.
// xw0h[M,128] = fp16( X[M,256] @ W0[256,128] )
// ---------------------------------------------------------------------------
#define G1_LDA 40    // 32 + 8 halves
#define G1_LDB 136   // 128 + 8 halves
#define G1_LDC 72    // 64 + 8 floats (epilogue staging, per column-half)
#define G1_C_BYTES  (128 * G1_LDC * 4)                     // 36864

__global__ void gemm1_wmma_kernel(const float* __restrict__ X,
                                  const float* __restrict__ W0) {
    __shared__ __align__(16) char smem[G1_C_BYTES];        // 36 KB (union)
    half*  As = (half*)smem;                               // [128][40]
    half*  Bs = (half*)(smem + 128 * G1_LDA * 2);          // [32][136]
    float* Cs = (float*)smem;                              // [128][72]

    const int tid   = threadIdx.x;
    const int warp  = tid >> 5;
    const int warpM = warp >> 1;        // 0..3
    const int warpN = warp & 1;         // 0..1
    const int bm    = blockIdx.x * 128;

    wmma::fragment<wmma::accumulator, 16, 16, 16, float> c[2][4];
#pragma unroll
    for (int i = 0; i < 2; i++)
#pragma unroll
        for (int j = 0; j < 4; j++) wmma::fill_fragment(c[i][j], 0.f);

    for (int k0 = 0; k0 < D_FEAT; k0 += 32) {
        // As: 128x32 fp32 -> fp16
#pragma unroll
        for (int t = 0; t < 4; t++) {
            int chunk = tid + t * 256;
            int row = chunk >> 3;
            int c4  = chunk & 7;
            int grow = bm + row;
            float4 v = make_float4(0.f, 0.f, 0.f, 0.f);
            if (grow < N_NODES)
                v = *(const float4*)(X + (size_t)grow * D_FEAT + k0 + c4 * 4);
            __half2 h0 = __floats2half2_rn(v.x, v.y);
            __half2 h1 = __floats2half2_rn(v.z, v.w);
            uint2 pk;
            pk.x = *(unsigned*)&h0;
            pk.y = *(unsigned*)&h1;
            *(uint2*)(As + (size_t)row * G1_LDA + c4 * 4) = pk;
        }
        // Bs: 32x128 fp32 -> fp16
#pragma unroll
        for (int t = 0; t < 4; t++) {
            int chunk = tid + t * 256;
            int row = chunk >> 5;
            int c4  = chunk & 31;
            float4 v = *(const float4*)(W0 + (size_t)(k0 + row) * H1 + c4 * 4);
            __half2 h0 = __floats2half2_rn(v.x, v.y);
            __half2 h1 = __floats2half2_rn(v.z, v.w);
            uint2 pk;
            pk.x = *(unsigned*)&h0;
            pk.y = *(unsigned*)&h1;
            *(uint2*)(Bs + (size_t)row * G1_LDB + c4 * 4) = pk;
        }
        __syncthreads();

#pragma unroll
        for (int kk = 0; kk < 32; kk += 16) {
            wmma::fragment<wmma::matrix_a, 16, 16, 16, half, wmma::row_major> a[2];
            wmma::fragment<wmma::matrix_b, 16, 16, 16, half, wmma::row_major> b[4];
#pragma unroll
            for (int i = 0; i < 2; i++)
                wmma::load_matrix_sync(a[i],
                    As + (size_t)(warpM * 32 + i * 16) * G1_LDA + kk, G1_LDA);
#pragma unroll
            for (int j = 0; j < 4; j++)
                wmma::load_matrix_sync(b[j],
                    Bs + (size_t)kk * G1_LDB + warpN * 64 + j * 16, G1_LDB);
#pragma unroll
            for (int i = 0; i < 2; i++)
#pragma unroll
                for (int j = 0; j < 4; j++)
                    wmma::mma_sync(c[i][j], a[i], b[j], c[i][j]);
        }
        __syncthreads();
    }

    // Epilogue in two column-halves through smem staging
#pragma unroll
    for (int p = 0; p < 2; p++) {
        if (warpN == p) {
#pragma unroll
            for (int i = 0; i < 2; i++)
#pragma unroll
                for (int j = 0; j < 4; j++)
                    wmma::store_matrix_sync(
                        Cs + (size_t)(warpM * 32 + i * 16) * G1_LDC + j * 16,
                        c[i][j], G1_LDC, wmma::mem_row_major);
        }
        __syncthreads();
#pragma unroll
        for (int t = 0; t < 8; t++) {
            int chunk = tid + t * 256;
            int row = chunk >> 4;
            int c4  = chunk & 15;
            int grow = bm + row;
            if (grow < N_NODES) {
                const float* s = Cs + (size_t)row * G1_LDC + c4 * 4;
                __half2 h0 = __floats2half2_rn(s[0], s[1]);
                __half2 h1 = __floats2half2_rn(s[2], s[3]);
                uint2 pk;
                pk.x = *(unsigned*)&h0;
                pk.y = *(unsigned*)&h1;
                *(uint2*)(g_xw0h + (size_t)grow * H1 + p * 64 + c4 * 4) = pk;
            }
        }
        __syncthreads();
    }
}

// ---------------------------------------------------------------------------
// FUSED layer-1 aggregate + layer-2 GEMM:
//   phase 1: per-warp CSR gather of 8 rows -> relu -> fp32 tile in smem
//   phase 2: block GEMM  hw1h[128,64] = fp16( tile[128,128] @ W1[128,64] )
// Block: 512 threads (16 warps), 128 rows; dyn smem = Hs[128][130] + W1s[128][64]
// ---------------------------------------------------------------------------
#define L1_ROWS    128
#define L1_THREADS 512
#define HS_STRIDE  130    // 520B rows: STS.64-aligned; 8/4-row offsets miss banks
#define L1_SMEM_BYTES ((L1_ROWS * HS_STRIDE + 128 * 64) * 4)   // 99,328 B

__global__ void layer1_fused_kernel(const float* __restrict__ W1) {
    extern __shared__ float fsm[];
    float* Hs  = fsm;                         // [128][130]
    float* W1s = fsm + L1_ROWS * HS_STRIDE;   // [128][64]

    const int tid  = threadIdx.x;
    const int warp = tid >> 5;
    const int lane = tid & 31;
    const int bm   = blockIdx.x * L1_ROWS;

    // stage W1 (runs concurrently with gather; both complete at barrier)
    for (int i = tid; i < 128 * 64 / 4; i += L1_THREADS)
        ((float4*)W1s)[i] = ((const float4*)W1)[i];

    // ---- phase 1: gather 8 rows per warp ----
    const uint2* __restrict__ h4 = (const uint2*)g_xw0h;   // 4 halves / elem
#pragma unroll 1
    for (int r = warp * 8; r < warp * 8 + 8; r++) {
        int row = bm + r;
        float4 acc = make_float4(0.f, 0.f, 0.f, 0.f);
        if (row < N_NODES) {
            int p  = g_ptr[row];
            int pe = g_ptr[row + 1];
            for (; p + 4 <= pe; p += 4) {
                int2 e0 = g_edge[p],     e1 = g_edge[p + 1];
                int2 e2 = g_edge[p + 2], e3 = g_edge[p + 3];
                uint2 r0 = h4[(size_t)e0.x * 32 + lane];
                uint2 r1 = h4[(size_t)e1.x * 32 + lane];
                uint2 r2 = h4[(size_t)e2.x * 32 + lane];
                uint2 r3 = h4[(size_t)e3.x * 32 + lane];
                float w0 = __int_as_float(e0.y), w1 = __int_as_float(e1.y);
                float w2 = __int_as_float(e2.y), w3 = __int_as_float(e3.y);
                float2 a0 = __half22float2(*(__half2*)&r0.x);
                float2 b0 = __half22float2(*(__half2*)&r0.y);
                float2 a1 = __half22float2(*(__half2*)&r1.x);
                float2 b1 = __half22float2(*(__half2*)&r1.y);
                float2 a2 = __half22float2(*(__half2*)&r2.x);
                float2 b2 = __half22float2(*(__half2*)&r2.y);
                float2 a3 = __half22float2(*(__half2*)&r3.x);
                float2 b3 = __half22float2(*(__half2*)&r3.y);
                acc.x += w0 * a0.x + w1 * a1.x + w2 * a2.x + w3 * a3.x;
                acc.y += w0 * a0.y + w1 * a1.y + w2 * a2.y + w3 * a3.y;
                acc.z += w0 * b0.x + w1 * b1.x + w2 * b2.x + w3 * b3.x;
                acc.w += w0 * b0.y + w1 * b1.y + w2 * b2.y + w3 * b3.y;
            }
            for (; p < pe; p++) {
                int2 e = g_edge[p];
                float w = __int_as_float(e.y);
                uint2 rr = h4[(size_t)e.x * 32 + lane];
                float2 a = __half22float2(*(__half2*)&rr.x);
                float2 b = __half22float2(*(__half2*)&rr.y);
                acc.x += w * a.x; acc.y += w * a.y;
                acc.z += w * b.x; acc.w += w * b.y;
            }
        }
        // relu + store to tile (two STS.64; 520B row stride)
        float* dst = Hs + r * HS_STRIDE + lane * 4;
        *(float2*)(dst)     = make_float2(fmaxf(acc.x, 0.f), fmaxf(acc.y, 0.f));
        *(float2*)(dst + 2) = make_float2(fmaxf(acc.z, 0.f), fmaxf(acc.w, 0.f));
    }
    __syncthreads();

    // ---- phase 2: tile[128,128] @ W1s[128,64] with f32x2 ----
    const int tx = tid & 15;    // col group: cols tx*4 .. tx*4+3
    const int ty = tid >> 4;    // row group: rows ty*4 .. ty*4+3
    unsigned long long acc2[4][2];
#pragma unroll
    for (int i = 0; i < 4; i++) { acc2[i][0] = 0ull; acc2[i][1] = 0ull; }

#pragma unroll 4
    for (int k = 0; k < 128; k++) {
        unsigned long long b0 =
            *(const unsigned long long*)(W1s + k * 64 + tx * 4);
        unsigned long long b1 =
            *(const unsigned long long*)(W1s + k * 64 + tx * 4 + 2);
#pragma unroll
        for (int i = 0; i < 4; i++) {
            float a = Hs[(ty * 4 + i) * HS_STRIDE + k];
            unsigned long long a2 = pack2(a, a);
            fma2(acc2[i][0], a2, b0);
            fma2(acc2[i][1], a2, b1);
        }
    }

#pragma unroll
    for (int i = 0; i < 4; i++) {
        int row = bm + ty * 4 + i;
        if (row < N_NODES) {
            float x0, x1, x2, x3;
            unpack2(acc2[i][0], x0, x1);
            unpack2(acc2[i][1], x2, x3);
            __half2 h0 = __floats2half2_rn(x0, x1);
            __half2 h1 = __floats2half2_rn(x2, x3);
            uint2 pk;
            pk.x = *(unsigned*)&h0;
            pk.y = *(unsigned*)&h1;
            *(uint2*)(g_hw1h + (size_t)row * H2 + tx * 4) = pk;
        }
    }
}

// ---------------------------------------------------------------------------
// CSR SPMM layer 2 fused with relu + softmax, F=64 halves.
// ---------------------------------------------------------------------------
__global__ void spmm2_softmax_kernel(float* __restrict__ out)
{
    int warp = (int)(((long long)blockIdx.x * blockDim.x + threadIdx.x) >> 5);
    int lane = threadIdx.x & 31;
    if (warp >= N_NODES) return;
    int p  = g_ptr[warp];
    int pe = g_ptr[warp + 1];
    const unsigned* __restrict__ h2p = (const unsigned*)g_hw1h;  // 2 halves
    float2 acc = make_float2(0.f, 0.f);

    for (; p + 4 <= pe; p += 4) {
        int2 e0 = g_edge[p],     e1 = g_edge[p + 1];
        int2 e2 = g_edge[p + 2], e3 = g_edge[p + 3];
        unsigned r0 = h2p[(size_t)e0.x * 32 + lane];
        unsigned r1 = h2p[(size_t)e1.x * 32 + lane];
        unsigned r2 = h2p[(size_t)e2.x * 32 + lane];
        unsigned r3 = h2p[(size_t)e3.x * 32 + lane];
        float w0 = __int_as_float(e0.y), w1 = __int_as_float(e1.y);
        float w2 = __int_as_float(e2.y), w3 = __int_as_float(e3.y);
        float2 v0 = __half22float2(*(__half2*)&r0);
        float2 v1 = __half22float2(*(__half2*)&r1);
        float2 v2 = __half22float2(*(__half2*)&r2);
        float2 v3 = __half22float2(*(__half2*)&r3);
        acc.x += w0 * v0.x + w1 * v1.x + w2 * v2.x + w3 * v3.x;
        acc.y += w0 * v0.y + w1 * v1.y + w2 * v2.y + w3 * v3.y;
    }
    for (; p < pe; p++) {
        int2 e = g_edge[p];
        float w = __int_as_float(e.y);
        unsigned r = h2p[(size_t)e.x * 32 + lane];
        float2 v = __half22float2(*(__half2*)&r);
        acc.x += w * v.x; acc.y += w * v.y;
    }

    // relu + softmax over the 64 values held by the warp
    float v0 = fmaxf(acc.x, 0.f);
    float v1 = fmaxf(acc.y, 0.f);
    float m = fmaxf(v0, v1);
#pragma unroll
    for (int o = 16; o; o >>= 1) m = fmaxf(m, __shfl_xor_sync(~0u, m, o));
    float e0 = __expf(v0 - m);
    float e1 = __expf(v1 - m);
    float s = e0 + e1;
#pragma unroll
    for (int o = 16; o; o >>= 1) s += __shfl_xor_sync(~0u, s, o);
    float inv = 1.f / s;
    ((float2*)out)[(size_t)warp * 32 + lane] = make_float2(e0 * inv, e1 * inv);
}

// ---------------------------------------------------------------------------
// Launch
// ---------------------------------------------------------------------------
extern "C" void kernel_launch(void* const* d_in, const int* in_sizes, int n_in,
                              void* d_out, int out_size)
{
    // Identify inputs by element count (same logic that passed R3-R7).
    const float* x  = nullptr;
    const float* W0 = nullptr;
    const float* W1 = nullptr;
    const void*  edge_buf[3] = {nullptr, nullptr, nullptr};
    int          edge_sz [3] = {0, 0, 0};
    int n_edge_bufs = 0;

    for (int i = 0; i < n_in; i++) {
        int sz = in_sizes[i];
        if (sz == N_NODES * D_FEAT)       x  = (const float*)d_in[i];
        else if (sz == D_FEAT * H1)       W0 = (const float*)d_in[i];
        else if (sz == H1 * H2)           W1 = (const float*)d_in[i];
        else if (n_edge_bufs < 3) {
            edge_buf[n_edge_bufs] = d_in[i];
            edge_sz [n_edge_bufs] = sz;
            n_edge_bufs++;
        }
    }
    const void*  esrc = edge_buf[0];
    const void*  edst = edge_buf[1];
    const float* ew   = (const float*)edge_buf[2];
    if (edge_sz[0] != edge_sz[1] || edge_sz[1] != edge_sz[2]) {
        int wi = 0;
        if (edge_sz[1] < edge_sz[wi]) wi = 1;
        if (edge_sz[2] < edge_sz[wi]) wi = 2;
        const void* rest[2]; int r = 0;
        for (int i = 0; i < 3; i++) if (i != wi) rest[r++] = edge_buf[i];
        esrc = rest[0]; edst = rest[1];
        ew   = (const float*)edge_buf[wi];
    }
    float* out = (float*)d_out;
    const int E = N_EDGES;

    const int EBLK = (E + 255) / 256;
    const int NBLK = (N_NODES + 255) / 256;
    const int WBLK = (int)(((long long)N_NODES * 32 + 255) / 256);
    const int L1BLK = (N_NODES + L1_ROWS - 1) / L1_ROWS;

    // allow >48KB dynamic smem for the fused kernel (idempotent)
    cudaFuncSetAttribute(layer1_fused_kernel,
                         cudaFuncAttributeMaxDynamicSharedMemorySize,
                         L1_SMEM_BYTES);

    // dtype probe + zero + CSR build
    detect_zero_kernel<<<NBLK, 256>>>(esrc);
    hist_kernel<<<EBLK, 256>>>(edst, E);
    scan1_kernel<<<N_SCAN_BLOCKS, SCAN_BLK>>>();
    scan3_kernel<<<NBLK, 256>>>(E);
    scatter_kernel<<<EBLK, 256>>>(esrc, edst, ew, E);

    // layer 1 GEMM: xw0h = fp16(X @ W0) via tensor cores
    gemm1_wmma_kernel<<<(N_NODES + 127) / 128, 256>>>(x, W0);

    // fused: h1 = A @ xw0 (gather), hw1h = fp16(relu(h1) @ W1)
    layer1_fused_kernel<<<L1BLK, L1_THREADS, L1_SMEM_BYTES>>>(W1);

    // layer 2 aggregate + softmax: out = softmax(relu(A @ hw1))
    spmm2_softmax_kernel<<<WBLK, 256>>>(out);
}

// round 9
// speedup vs baseline: 1.0441x; 1.0441x over previous
#include <cuda_runtime.h>
#include <cuda_bf16.h>
#include <cuda_fp16.h>
#include <mma.h>
#include <cstdint>

using namespace nvcuda;

// Problem constants (fixed-shape problem, from reference_code)
#define N_NODES 100000
#define D_FEAT  256
#define H1      128
#define H2      64
#define N_EDGES 1600000

#define SCAN_BLK 1024
#define N_SCAN_BLOCKS ((N_NODES + SCAN_BLK - 1) / SCAN_BLK)   // 98

// Scratch buffers (device globals: allocation-free scratch).
__device__ __half g_xw0h[(size_t)N_NODES * H1];  // X @ W0, fp16 (gather operand)
__device__ float  g_h1 [(size_t)N_NODES * H1];   // spmm1 result fp32 (pre-relu)
__device__ __half g_hw1h[(size_t)N_NODES * H2];  // relu(h1) @ W1, fp16 (gather operand)
__device__ int    g_is64;                        // edge index dtype flag

// CSR (by dst) built fresh each launch; col+weight packed in one int2
__device__ int   g_cnt [N_NODES];                // histogram, then cursor
__device__ int   g_ptr [N_NODES + 1];            // row pointers
__device__ int   g_bsum[N_SCAN_BLOCKS];
__device__ int2  g_edge[N_EDGES];                // {col, __float_as_int(w)}

// ---------------------------------------------------------------------------
// f32x2 packed math (sm_103a; PTX-only — ptxas never auto-fuses)
// ---------------------------------------------------------------------------
__device__ __forceinline__ unsigned long long pack2(float x, float y) {
    unsigned long long r;
    asm("mov.b64 %0, {%1, %2};" : "=l"(r) : "f"(x), "f"(y));
    return r;
}
__device__ __forceinline__ void unpack2(unsigned long long v, float& x, float& y) {
    asm("mov.b64 {%0, %1}, %2;" : "=f"(x), "=f"(y) : "l"(v));
}
__device__ __forceinline__ void fma2(unsigned long long& d,
                                     unsigned long long a,
                                     unsigned long long b) {
    asm("fma.rn.f32x2 %0, %1, %2, %0;" : "+l"(d) : "l"(a), "l"(b));
}

// ---------------------------------------------------------------------------
// dtype probe (thread 0) + zero histogram (whole grid)
// ---------------------------------------------------------------------------
__global__ void detect_zero_kernel(const void* __restrict__ src) {
    int i = blockIdx.x * blockDim.x + threadIdx.x;
    if (i < N_NODES) g_cnt[i] = 0;
    if (i == 0) {
        const long long* p = (const long long*)src;
        int ok = 1;
        for (int k = 0; k < 64; k++) {
            long long v = p[k];
            if (v < 0 || v >= N_NODES) { ok = 0; break; }
        }
        g_is64 = ok;
    }
}

__device__ __forceinline__ int load_idx(const void* p, int e, int is64) {
    return is64 ? (int)((const long long*)p)[e] : ((const int*)p)[e];
}

// ---------------------------------------------------------------------------
// CSR build: histogram -> scan(2 kernels) -> scatter
// ---------------------------------------------------------------------------
__global__ void hist_kernel(const void* __restrict__ dst, int E) {
    int e = blockIdx.x * blockDim.x + threadIdx.x;
    if (e >= E) return;
    int d = load_idx(dst, e, g_is64);
    if ((unsigned)d < N_NODES) atomicAdd(&g_cnt[d], 1);
}

__global__ void scan1_kernel() {
    __shared__ int s[SCAN_BLK];
    int i = blockIdx.x * SCAN_BLK + threadIdx.x;
    int v = (i < N_NODES) ? g_cnt[i] : 0;
    s[threadIdx.x] = v;
    __syncthreads();
#pragma unroll
    for (int o = 1; o < SCAN_BLK; o <<= 1) {
        int t = (threadIdx.x >= o) ? s[threadIdx.x - o] : 0;
        __syncthreads();
        s[threadIdx.x] += t;
        __syncthreads();
    }
    int inc = s[threadIdx.x];
    if (i < N_NODES) g_ptr[i] = inc - v;
    if (threadIdx.x == SCAN_BLK - 1) g_bsum[blockIdx.x] = inc;
}

// scan3 with scan2 folded in
__global__ void scan3_kernel(int E) {
    __shared__ int soff[2];
    int base = blockIdx.x * blockDim.x;
    int b0 = base / SCAN_BLK;
    if (threadIdx.x < 2) {
        int b = b0 + threadIdx.x;
        int off = 0;
        for (int j = 0; j < b && j < N_SCAN_BLOCKS; j++) off += g_bsum[j];
        soff[threadIdx.x] = off;
    }
    __syncthreads();
    int i = base + threadIdx.x;
    if (i < N_NODES) {
        int p = g_ptr[i] + soff[i / SCAN_BLK - b0];
        g_ptr[i] = p;
        g_cnt[i] = p;                     // cursor for scatter
    }
    if (i == 0) g_ptr[N_NODES] = E;
}

__global__ void scatter_kernel(const void* __restrict__ src,
                               const void* __restrict__ dst,
                               const float* __restrict__ w, int E) {
    int e = blockIdx.x * blockDim.x + threadIdx.x;
    if (e >= E) return;
    int is64 = g_is64;
    int s = load_idx(src, e, is64);
    int d = load_idx(dst, e, is64);
    if ((unsigned)s >= N_NODES || (unsigned)d >= N_NODES) return;
    int pos = atomicAdd(&g_cnt[d], 1);
    g_edge[pos] = make_int2(s, __float_as_int(w[e]));
}

// ---------------------------------------------------------------------------
// GEMM1: tensor-core (wmma fp16 in / fp32 accum), output fp16.
// xw0h[M,128] = fp16( X[M,256] @ W0[256,128] )
// ---------------------------------------------------------------------------
#define G1_LDA 40    // 32 + 8 halves
#define G1_LDB 136   // 128 + 8 halves
#define G1_LDC 72    // 64 + 8 floats (epilogue staging, per column-half)
#define G1_C_BYTES  (128 * G1_LDC * 4)                     // 36864

__global__ void gemm1_wmma_kernel(const float* __restrict__ X,
                                  const float* __restrict__ W0) {
    __shared__ __align__(16) char smem[G1_C_BYTES];        // 36 KB (union)
    half*  As = (half*)smem;                               // [128][40]
    half*  Bs = (half*)(smem + 128 * G1_LDA * 2);          // [32][136]
    float* Cs = (float*)smem;                              // [128][72]

    const int tid   = threadIdx.x;
    const int warp  = tid >> 5;
    const int warpM = warp >> 1;        // 0..3
    const int warpN = warp & 1;         // 0..1
    const int bm    = blockIdx.x * 128;

    wmma::fragment<wmma::accumulator, 16, 16, 16, float> c[2][4];
#pragma unroll
    for (int i = 0; i < 2; i++)
#pragma unroll
        for (int j = 0; j < 4; j++) wmma::fill_fragment(c[i][j], 0.f);

    for (int k0 = 0; k0 < D_FEAT; k0 += 32) {
        // As: 128x32 fp32 -> fp16
#pragma unroll
        for (int t = 0; t < 4; t++) {
            int chunk = tid + t * 256;
            int row = chunk >> 3;
            int c4  = chunk & 7;
            int grow = bm + row;
            float4 v = make_float4(0.f, 0.f, 0.f, 0.f);
            if (grow < N_NODES)
                v = *(const float4*)(X + (size_t)grow * D_FEAT + k0 + c4 * 4);
            __half2 h0 = __floats2half2_rn(v.x, v.y);
            __half2 h1 = __floats2half2_rn(v.z, v.w);
            uint2 pk;
            pk.x = *(unsigned*)&h0;
            pk.y = *(unsigned*)&h1;
            *(uint2*)(As + (size_t)row * G1_LDA + c4 * 4) = pk;
        }
        // Bs: 32x128 fp32 -> fp16
#pragma unroll
        for (int t = 0; t < 4; t++) {
            int chunk = tid + t * 256;
            int row = chunk >> 5;
            int c4  = chunk & 31;
            float4 v = *(const float4*)(W0 + (size_t)(k0 + row) * H1 + c4 * 4);
            __half2 h0 = __floats2half2_rn(v.x, v.y);
            __half2 h1 = __floats2half2_rn(v.z, v.w);
            uint2 pk;
            pk.x = *(unsigned*)&h0;
            pk.y = *(unsigned*)&h1;
            *(uint2*)(Bs + (size_t)row * G1_LDB + c4 * 4) = pk;
        }
        __syncthreads();

#pragma unroll
        for (int kk = 0; kk < 32; kk += 16) {
            wmma::fragment<wmma::matrix_a, 16, 16, 16, half, wmma::row_major> a[2];
            wmma::fragment<wmma::matrix_b, 16, 16, 16, half, wmma::row_major> b[4];
#pragma unroll
            for (int i = 0; i < 2; i++)
                wmma::load_matrix_sync(a[i],
                    As + (size_t)(warpM * 32 + i * 16) * G1_LDA + kk, G1_LDA);
#pragma unroll
            for (int j = 0; j < 4; j++)
                wmma::load_matrix_sync(b[j],
                    Bs + (size_t)kk * G1_LDB + warpN * 64 + j * 16, G1_LDB);
#pragma unroll
            for (int i = 0; i < 2; i++)
#pragma unroll
                for (int j = 0; j < 4; j++)
                    wmma::mma_sync(c[i][j], a[i], b[j], c[i][j]);
        }
        __syncthreads();
    }

    // Epilogue in two column-halves through smem staging
#pragma unroll
    for (int p = 0; p < 2; p++) {
        if (warpN == p) {
#pragma unroll
            for (int i = 0; i < 2; i++)
#pragma unroll
                for (int j = 0; j < 4; j++)
                    wmma::store_matrix_sync(
                        Cs + (size_t)(warpM * 32 + i * 16) * G1_LDC + j * 16,
                        c[i][j], G1_LDC, wmma::mem_row_major);
        }
        __syncthreads();
#pragma unroll
        for (int t = 0; t < 8; t++) {
            int chunk = tid + t * 256;
            int row = chunk >> 4;
            int c4  = chunk & 15;
            int grow = bm + row;
            if (grow < N_NODES) {
                const float* s = Cs + (size_t)row * G1_LDC + c4 * 4;
                __half2 h0 = __floats2half2_rn(s[0], s[1]);
                __half2 h1 = __floats2half2_rn(s[2], s[3]);
                uint2 pk;
                pk.x = *(unsigned*)&h0;
                pk.y = *(unsigned*)&h1;
                *(uint2*)(g_xw0h + (size_t)grow * H1 + p * 64 + c4 * 4) = pk;
            }
        }
        __syncthreads();
    }
}

// ---------------------------------------------------------------------------
// GEMM2 (f32x2, register-blocked): hw1h = fp16( relu(h1) @ W1 )
// ---------------------------------------------------------------------------
template<int BM, int BN, int BK, int TM, int TN, bool RELU_A>
__device__ __forceinline__ void gemm_body_h(const float* __restrict__ A,
                                            const float* __restrict__ B,
                                            __half* __restrict__ C,
                                            int M, int K, int N)
{
    __shared__ float As[BK][BM];   // transposed A tile
    __shared__ float Bs[BK][BN];

    constexpr int THREADS = (BM / TM) * (BN / TN);   // 256
    const int tid = threadIdx.x;
    const int bm  = blockIdx.x * BM;
    const int tx  = tid % (BN / TN);
    const int ty  = tid / (BN / TN);

    unsigned long long acc2[TM][TN / 2];
#pragma unroll
    for (int i = 0; i < TM; i++)
#pragma unroll
        for (int j = 0; j < TN / 2; j++) acc2[i][j] = 0ull;

    for (int k0 = 0; k0 < K; k0 += BK) {
        constexpr int A_ELEMS = BM * BK;
#pragma unroll
        for (int off = 0; off < A_ELEMS; off += THREADS * 4) {
            int idx = off + tid * 4;
            if (idx < A_ELEMS) {
                int ar  = idx / BK;
                int ac  = idx % BK;
                int grow = bm + ar;
                float4 v = make_float4(0.f, 0.f, 0.f, 0.f);
                if (grow < M)
                    v = *(const float4*)(A + (size_t)grow * K + k0 + ac);
                if (RELU_A) {
                    v.x = fmaxf(v.x, 0.f); v.y = fmaxf(v.y, 0.f);
                    v.z = fmaxf(v.z, 0.f); v.w = fmaxf(v.w, 0.f);
                }
                As[ac + 0][ar] = v.x;
                As[ac + 1][ar] = v.y;
                As[ac + 2][ar] = v.z;
                As[ac + 3][ar] = v.w;
            }
        }
        constexpr int B_ELEMS = BK * BN;
#pragma unroll
        for (int off = 0; off < B_ELEMS; off += THREADS * 4) {
            int idx = off + tid * 4;
            if (idx < B_ELEMS) {
                int br = idx / BN;
                int bc = idx % BN;
                *(float4*)&Bs[br][bc] =
                    *(const float4*)(B + (size_t)(k0 + br) * N + bc);
            }
        }
        __syncthreads();

#pragma unroll
        for (int kk = 0; kk < BK; kk++) {
            unsigned long long b2[TN / 2];
#pragma unroll
            for (int j = 0; j < TN / 2; j++)
                b2[j] = *(const unsigned long long*)&Bs[kk][tx * TN + 2 * j];
#pragma unroll
            for (int i = 0; i < TM; i++) {
                float a = As[kk][ty * TM + i];
                unsigned long long a2 = pack2(a, a);
#pragma unroll
                for (int j = 0; j < TN / 2; j++)
                    fma2(acc2[i][j], a2, b2[j]);
            }
        }
        __syncthreads();
    }

#pragma unroll
    for (int i = 0; i < TM; i++) {
        int row = bm + ty * TM + i;
        if (row < M) {
            __half2 h[TN / 2];
#pragma unroll
            for (int j = 0; j < TN / 2; j++) {
                float lo, hi;
                unpack2(acc2[i][j], lo, hi);
                h[j] = __floats2half2_rn(lo, hi);
            }
#pragma unroll
            for (int j = 0; j < TN / 2; j += 2)
                *(uint2*)(C + (size_t)row * N + tx * TN + 2 * j) =
                    *(uint2*)&h[j];
        }
    }
}

__global__ void gemm2_kernel(const float* __restrict__ W1) {
    gemm_body_h<128, 64, 32, 8, 4, true>(g_h1, W1, g_hw1h, N_NODES, H1, H2);
}

// ---------------------------------------------------------------------------
// CSR SPMM layer 1: h1[r] = sum_e w_e * xw0[col_e], F=128 halves.
// One warp per row; 8-edge batches for deep MLP.
// ---------------------------------------------------------------------------
__global__ void spmm1_csr_kernel()
{
    int warp = (int)(((long long)blockIdx.x * blockDim.x + threadIdx.x) >> 5);
    int lane = threadIdx.x & 31;
    if (warp >= N_NODES) return;
    int p  = g_ptr[warp];
    int pe = g_ptr[warp + 1];
    const uint2* __restrict__ h4 = (const uint2*)g_xw0h;   // 4 halves / elem
    float4 acc = make_float4(0.f, 0.f, 0.f, 0.f);

    for (; p + 8 <= pe; p += 8) {
        int2  e[8];
        uint2 r[8];
#pragma unroll
        for (int j = 0; j < 8; j++) e[j] = g_edge[p + j];
#pragma unroll
        for (int j = 0; j < 8; j++) r[j] = h4[(size_t)e[j].x * 32 + lane];
#pragma unroll
        for (int j = 0; j < 8; j++) {
            float w = __int_as_float(e[j].y);
            float2 a = __half22float2(*(__half2*)&r[j].x);
            float2 b = __half22float2(*(__half2*)&r[j].y);
            acc.x += w * a.x; acc.y += w * a.y;
            acc.z += w * b.x; acc.w += w * b.y;
        }
    }
    if (p + 4 <= pe) {
        int2  e[4];
        uint2 r[4];
#pragma unroll
        for (int j = 0; j < 4; j++) e[j] = g_edge[p + j];
#pragma unroll
        for (int j = 0; j < 4; j++) r[j] = h4[(size_t)e[j].x * 32 + lane];
#pragma unroll
        for (int j = 0; j < 4; j++) {
            float w = __int_as_float(e[j].y);
            float2 a = __half22float2(*(__half2*)&r[j].x);
            float2 b = __half22float2(*(__half2*)&r[j].y);
            acc.x += w * a.x; acc.y += w * a.y;
            acc.z += w * b.x; acc.w += w * b.y;
        }
        p += 4;
    }
    for (; p < pe; p++) {
        int2 e = g_edge[p];
        float w = __int_as_float(e.y);
        uint2 r = h4[(size_t)e.x * 32 + lane];
        float2 a = __half22float2(*(__half2*)&r.x);
        float2 b = __half22float2(*(__half2*)&r.y);
        acc.x += w * a.x; acc.y += w * a.y;
        acc.z += w * b.x; acc.w += w * b.y;
    }
    ((float4*)g_h1)[(size_t)warp * 32 + lane] = acc;
}

// ---------------------------------------------------------------------------
// CSR SPMM layer 2 fused with relu + softmax, F=64 halves; 8-edge batches.
// ---------------------------------------------------------------------------
__global__ void spmm2_softmax_kernel(float* __restrict__ out)
{
    int warp = (int)(((long long)blockIdx.x * blockDim.x + threadIdx.x) >> 5);
    int lane = threadIdx.x & 31;
    if (warp >= N_NODES) return;
    int p  = g_ptr[warp];
    int pe = g_ptr[warp + 1];
    const unsigned* __restrict__ h2p = (const unsigned*)g_hw1h;  // 2 halves
    float2 acc = make_float2(0.f, 0.f);

    for (; p + 8 <= pe; p += 8) {
        int2     e[8];
        unsigned r[8];
#pragma unroll
        for (int j = 0; j < 8; j++) e[j] = g_edge[p + j];
#pragma unroll
        for (int j = 0; j < 8; j++) r[j] = h2p[(size_t)e[j].x * 32 + lane];
#pragma unroll
        for (int j = 0; j < 8; j++) {
            float w = __int_as_float(e[j].y);
            float2 v = __half22float2(*(__half2*)&r[j]);
            acc.x += w * v.x; acc.y += w * v.y;
        }
    }
    if (p + 4 <= pe) {
        int2     e[4];
        unsigned r[4];
#pragma unroll
        for (int j = 0; j < 4; j++) e[j] = g_edge[p + j];
#pragma unroll
        for (int j = 0; j < 4; j++) r[j] = h2p[(size_t)e[j].x * 32 + lane];
#pragma unroll
        for (int j = 0; j < 4; j++) {
            float w = __int_as_float(e[j].y);
            float2 v = __half22float2(*(__half2*)&r[j]);
            acc.x += w * v.x; acc.y += w * v.y;
        }
        p += 4;
    }
    for (; p < pe; p++) {
        int2 e = g_edge[p];
        float w = __int_as_float(e.y);
        unsigned r = h2p[(size_t)e.x * 32 + lane];
        float2 v = __half22float2(*(__half2*)&r);
        acc.x += w * v.x; acc.y += w * v.y;
    }

    // relu + softmax over the 64 values held by the warp
    float v0 = fmaxf(acc.x, 0.f);
    float v1 = fmaxf(acc.y, 0.f);
    float m = fmaxf(v0, v1);
#pragma unroll
    for (int o = 16; o; o >>= 1) m = fmaxf(m, __shfl_xor_sync(~0u, m, o));
    float e0 = __expf(v0 - m);
    float e1 = __expf(v1 - m);
    float s = e0 + e1;
#pragma unroll
    for (int o = 16; o; o >>= 1) s += __shfl_xor_sync(~0u, s, o);
    float inv = 1.f / s;
    ((float2*)out)[(size_t)warp * 32 + lane] = make_float2(e0 * inv, e1 * inv);
}

// ---------------------------------------------------------------------------
// Launch: fork-join streams — gemm1 (tensor) overlaps CSR build (memory)
// ---------------------------------------------------------------------------
extern "C" void kernel_launch(void* const* d_in, const int* in_sizes, int n_in,
                              void* d_out, int out_size)
{
    // Identify inputs by element count (same logic that passed R3-R8).
    const float* x  = nullptr;
    const float* W0 = nullptr;
    const float* W1 = nullptr;
    const void*  edge_buf[3] = {nullptr, nullptr, nullptr};
    int          edge_sz [3] = {0, 0, 0};
    int n_edge_bufs = 0;

    for (int i = 0; i < n_in; i++) {
        int sz = in_sizes[i];
        if (sz == N_NODES * D_FEAT)       x  = (const float*)d_in[i];
        else if (sz == D_FEAT * H1)       W0 = (const float*)d_in[i];
        else if (sz == H1 * H2)           W1 = (const float*)d_in[i];
        else if (n_edge_bufs < 3) {
            edge_buf[n_edge_bufs] = d_in[i];
            edge_sz [n_edge_bufs] = sz;
            n_edge_bufs++;
        }
    }
    const void*  esrc = edge_buf[0];
    const void*  edst = edge_buf[1];
    const float* ew   = (const float*)edge_buf[2];
    if (edge_sz[0] != edge_sz[1] || edge_sz[1] != edge_sz[2]) {
        int wi = 0;
        if (edge_sz[1] < edge_sz[wi]) wi = 1;
        if (edge_sz[2] < edge_sz[wi]) wi = 2;
        const void* rest[2]; int r = 0;
        for (int i = 0; i < 3; i++) if (i != wi) rest[r++] = edge_buf[i];
        esrc = rest[0]; edst = rest[1];
        ew   = (const float*)edge_buf[wi];
    }
    float* out = (float*)d_out;
    const int E = N_EDGES;

    const int EBLK = (E + 255) / 256;
    const int NBLK = (N_NODES + 255) / 256;
    const int WBLK = (int)(((long long)N_NODES * 32 + 255) / 256);

    // Fork-join side stream for gemm1 (created/destroyed per call; no caching)
    cudaStream_t s2 = nullptr;
    cudaEvent_t  evFork = nullptr, evJoin = nullptr;
    bool overlap = (cudaStreamCreateWithFlags(&s2, cudaStreamNonBlocking)
                        == cudaSuccess);
    if (overlap) {
        overlap = (cudaEventCreateWithFlags(&evFork, cudaEventDisableTiming)
                       == cudaSuccess) &&
                  (cudaEventCreateWithFlags(&evJoin, cudaEventDisableTiming)
                       == cudaSuccess);
    }

    if (overlap) {
        cudaEventRecord(evFork, 0);            // fork from capture stream
        cudaStreamWaitEvent(s2, evFork, 0);
        gemm1_wmma_kernel<<<(N_NODES + 127) / 128, 256, 0, s2>>>(x, W0);
        cudaEventRecord(evJoin, s2);
    } else {
        gemm1_wmma_kernel<<<(N_NODES + 127) / 128, 256>>>(x, W0);
    }

    // CSR build on the main (capture) stream
    detect_zero_kernel<<<NBLK, 256>>>(esrc);
    hist_kernel<<<EBLK, 256>>>(edst, E);
    scan1_kernel<<<N_SCAN_BLOCKS, SCAN_BLK>>>();
    scan3_kernel<<<NBLK, 256>>>(E);
    scatter_kernel<<<EBLK, 256>>>(esrc, edst, ew, E);

    if (overlap)
        cudaStreamWaitEvent(0, evJoin, 0);     // join before spmm1

    // layer 1 aggregate: h1 = A @ xw0 (CSR gather, fp32 acc)
    spmm1_csr_kernel<<<WBLK, 256>>>();

    // layer 2: hw1h = fp16(relu(h1) @ W1), then out = softmax(relu(A @ hw1))
    gemm2_kernel<<<(N_NODES + 127) / 128, 256>>>(W1);
    spmm2_softmax_kernel<<<WBLK, 256>>>(out);

    if (evFork) cudaEventDestroy(evFork);
    if (evJoin) cudaEventDestroy(evJoin);
    if (s2)     cudaStreamDestroy(s2);
}